// round 2
// baseline (speedup 1.0000x reference)
#include <cuda_runtime.h>
#include <cuda_bf16.h>
#include <stdint.h>

// Problem constants
#define NUM_QT   65
#define NUM_OT   151
#define PAIR_NUM 90
#define BATCH    8192
#define BOX      10
// out elements = NUM_QT * PAIR_NUM * NUM_OT * NUM_OT = 133,385,850

__global__ void scatter_add_kernel(const int* __restrict__ obj_label,   // [BATCH, BOX]
                                   const int* __restrict__ qus_type,    // [BATCH]
                                   const float* __restrict__ attention, // [BATCH, BOX]
                                   float* __restrict__ out)             // [NUM_QT, PAIR_NUM, NUM_OT, NUM_OT]
{
    int t = blockIdx.x * blockDim.x + threadIdx.x;
    const int total = BATCH * PAIR_NUM;
    if (t >= total) return;

    int b = t / PAIR_NUM;
    int p = t - b * PAIR_NUM;

    int i  = p / (BOX - 1);
    int jj = p - i * (BOX - 1);
    int j  = jj + (jj >= i ? 1 : 0);

    // Gathered indices per reference:
    //   ol1[b,p] = obj_label[b, j]   (jidx gather)
    //   ol2[b,p] = obj_label[b, i]   (repeat)
    //   at = attention[b,j] * attention[b,i]
    int ol1 = obj_label[b * BOX + j];
    int ol2 = obj_label[b * BOX + i];
    int qt  = qus_type[b];
    float a = attention[b * BOX + j] * attention[b * BOX + i];

    long long idx = (((long long)qt * PAIR_NUM + p) * NUM_OT + ol1) * NUM_OT + ol2;
    atomicAdd(&out[idx], a);
}

extern "C" void kernel_launch(void* const* d_in, const int* in_sizes, int n_in,
                              void* d_out, int out_size)
{
    // metadata order: obj_label (int32), qus_type (int32), attention (f32), score_matrix (f32)
    const int*   obj_label = (const int*)d_in[0];
    const int*   qus_type  = (const int*)d_in[1];
    const float* attention = (const float*)d_in[2];
    const float* score     = (const float*)d_in[3];
    float* out = (float*)d_out;

    // 1) Bulk copy score_matrix -> out (HBM-bound, ~1.07 GB traffic)
    size_t bytes = (size_t)out_size * sizeof(float);
    cudaMemcpyAsync(out, score, bytes, cudaMemcpyDeviceToDevice, 0);

    // 2) Sparse scatter-add (737,280 atomics; negligible next to the copy)
    const int total = BATCH * PAIR_NUM;
    const int threads = 256;
    const int blocks = (total + threads - 1) / threads;
    scatter_add_kernel<<<blocks, threads, 0, 0>>>(obj_label, qus_type, attention, out);
}

// round 4
// speedup vs baseline: 1.8970x; 1.8970x over previous
#include <cuda_runtime.h>
#include <cuda_bf16.h>
#include <stdint.h>

// Problem constants
#define NUM_QT   65
#define NUM_OT   151
#define PAIR_NUM 90
#define BATCH    8192
#define BOX      10
// out elements = NUM_QT * PAIR_NUM * NUM_OT * NUM_OT = 133,385,850

// ---------------------------------------------------------------------------
// Bulk copy: score_matrix -> out. float4 grid-stride, streaming cache hints.
// 1.07 GB total HBM traffic; target ~6.3 TB/s achieved -> ~170 us.
// ---------------------------------------------------------------------------
__global__ void copy_kernel(const float4* __restrict__ src,
                            float4* __restrict__ dst,
                            long long n4,
                            const float* __restrict__ src_tail,
                            float* __restrict__ dst_tail,
                            int tail)
{
    long long stride = (long long)gridDim.x * blockDim.x;
    long long i = (long long)blockIdx.x * blockDim.x + threadIdx.x;
    // Unrolled-by-4 grid-stride for MLP (independent loads in flight)
    for (; i + 3 * stride < n4; i += 4 * stride) {
        float4 a = __ldcs(&src[i]);
        float4 b = __ldcs(&src[i + stride]);
        float4 c = __ldcs(&src[i + 2 * stride]);
        float4 d = __ldcs(&src[i + 3 * stride]);
        __stcs(&dst[i],              a);
        __stcs(&dst[i + stride],     b);
        __stcs(&dst[i + 2 * stride], c);
        __stcs(&dst[i + 3 * stride], d);
    }
    for (; i < n4; i += stride) {
        __stcs(&dst[i], __ldcs(&src[i]));
    }
    // Tail (out_size % 4 elements), handled by the first few threads
    long long t = (long long)blockIdx.x * blockDim.x + threadIdx.x;
    if (t < tail) {
        dst_tail[t] = src_tail[t];
    }
}

// ---------------------------------------------------------------------------
// Sparse scatter-add: 737,280 atomics into the 133M-cell table.
// ---------------------------------------------------------------------------
__global__ void scatter_add_kernel(const int* __restrict__ obj_label,   // [BATCH, BOX]
                                   const int* __restrict__ qus_type,    // [BATCH]
                                   const float* __restrict__ attention, // [BATCH, BOX]
                                   float* __restrict__ out)             // [NUM_QT, PAIR_NUM, NUM_OT, NUM_OT]
{
    int t = blockIdx.x * blockDim.x + threadIdx.x;
    const int total = BATCH * PAIR_NUM;
    if (t >= total) return;

    int b = t / PAIR_NUM;
    int p = t - b * PAIR_NUM;

    int i  = p / (BOX - 1);
    int jj = p - i * (BOX - 1);
    int j  = jj + (jj >= i ? 1 : 0);

    // ol1[b,p] = obj_label[b, j] (jidx gather); ol2[b,p] = obj_label[b, i] (repeat)
    int ol1 = obj_label[b * BOX + j];
    int ol2 = obj_label[b * BOX + i];
    int qt  = qus_type[b];
    float a = attention[b * BOX + j] * attention[b * BOX + i];

    long long idx = (((long long)qt * PAIR_NUM + p) * NUM_OT + ol1) * NUM_OT + ol2;
    atomicAdd(&out[idx], a);
}

extern "C" void kernel_launch(void* const* d_in, const int* in_sizes, int n_in,
                              void* d_out, int out_size)
{
    // metadata order: obj_label (int32), qus_type (int32), attention (f32), score_matrix (f32)
    const int*   obj_label = (const int*)d_in[0];
    const int*   qus_type  = (const int*)d_in[1];
    const float* attention = (const float*)d_in[2];
    const float* score     = (const float*)d_in[3];
    float* out = (float*)d_out;

    // 1) Bulk copy via SM path (copy-engine memcpy node measured ~3.1 TB/s only)
    long long n  = (long long)out_size;
    long long n4 = n >> 2;            // float4 count
    int tail     = (int)(n & 3);      // leftover floats
    const float* src_tail = score + (n4 << 2);
    float*       dst_tail = out   + (n4 << 2);

    const int cthreads = 256;
    // Full-chip wave count: 148 SMs * up to 8 blocks of 256 -> grid-stride covers rest
    int cblocks = 148 * 8;
    copy_kernel<<<cblocks, cthreads, 0, 0>>>((const float4*)score, (float4*)out,
                                             n4, src_tail, dst_tail, tail);

    // 2) Sparse scatter-add after the copy (same stream ordering)
    const int total = BATCH * PAIR_NUM;
    const int threads = 256;
    const int blocks = (total + threads - 1) / threads;
    scatter_add_kernel<<<blocks, threads, 0, 0>>>(obj_label, qus_type, attention, out);
}